// round 8
// baseline (speedup 1.0000x reference)
#include <cuda_runtime.h>
#include <cuda_bf16.h>
#include <cstdint>

// ---------------- problem constants ----------------
#define kB   2
#define kN   16384
#define kDIM 512
#define kH   8
#define kROWS (kB * kN)          // 32768
#define kBH   (kB * kH)          // 16
#define kSLOTS 256               // enc partial slots (128 chunks x 2 warp-halves)

// ---------------- scratch (device globals) ----------------
__device__ ushort g_xh[kROWS * kDIM],  g_xl[kROWS * kDIM];      // xmid hi/lo
__device__ ushort g_mixh[kROWS * kDIM], g_mixl[kROWS * kDIM];   // gated mix hi/lo
__device__ ushort g_kh[kBH * kN * 64], g_kl[kBH * kN * 64];
__device__ ushort g_qh[kBH * kN * 64], g_ql[kBH * kN * 64];
__device__ ushort g_qgh[512 * 64], g_qgl[512 * 64];             // [h*64+m][d]
__device__ ushort g_kch[kBH * 4096], g_kcl[kBH * 4096];         // [bh][s][d]
__device__ ushort g_vcth[kBH * 4096], g_vctl[kBH * 4096];       // [bh][d][s]
__device__ ushort g_lath[kBH * 4096], g_latl[kBH * 4096];       // latent^T [bh][d][m]
__device__ ushort g_wkvqh[192 * 64], g_wkvql[192 * 64];         // [col(k|v|q)][din]
__device__ ushort g_whi[kDIM * kDIM], g_wlo[kDIM * kDIM];       // proj W split
__device__ float  g_psum[kSLOTS * kBH * 64];
__device__ float  g_pacc[(size_t)kSLOTS * kBH * 4096];          // 67 MB

// ---------------- helpers ----------------
__device__ __forceinline__ ushort bfhi(float x) {
  return __bfloat16_as_ushort(__float2bfloat16(x));
}
__device__ __forceinline__ float bfval(ushort u) {
  return __bfloat162float(__ushort_as_bfloat16(u));
}
__device__ __forceinline__ void split2(float a, float b, uint32_t& hi, uint32_t& lo) {
  ushort ha = bfhi(a), hb = bfhi(b);
  hi = (uint32_t)ha | ((uint32_t)hb << 16);
  lo = (uint32_t)bfhi(a - bfval(ha)) | ((uint32_t)bfhi(b - bfval(hb)) << 16);
}
__device__ __forceinline__ void mma_bf16(float* d, const uint32_t* a,
                                         const uint32_t* b) {
  asm volatile(
      "mma.sync.aligned.m16n8k16.row.col.f32.bf16.bf16.f32 "
      "{%0,%1,%2,%3}, {%4,%5,%6,%7}, {%8,%9}, {%0,%1,%2,%3};"
      : "+f"(d[0]), "+f"(d[1]), "+f"(d[2]), "+f"(d[3])
      : "r"(a[0]), "r"(a[1]), "r"(a[2]), "r"(a[3]), "r"(b[0]), "r"(b[1]));
}
__device__ __forceinline__ uint32_t s2u(const void* p) {
  return (uint32_t)__cvta_generic_to_shared(p);
}
__device__ __forceinline__ void ldsm_x4(uint32_t* r, uint32_t addr) {
  asm volatile(
      "ldmatrix.sync.aligned.m8n8.x4.shared.b16 {%0,%1,%2,%3}, [%4];"
      : "=r"(r[0]), "=r"(r[1]), "=r"(r[2]), "=r"(r[3]) : "r"(addr));
}
// ldmatrix lane selectors (validated mapping from mma512, rel_err-identical)
#define LDSM_SEL                                            \
  int lane_ = threadIdx.x & 31;                             \
  int a_row = lane_ & 15, a_w = (lane_ >> 4) * 4;           \
  int b_row = ((lane_ >> 4) << 3) + (lane_ & 7);            \
  int b_w = ((lane_ >> 3) & 1) * 4;

// load R rows x (w32 uint32) bf16 tile from gmem into smem with row stride sstr
__device__ __forceinline__ void load_tile(uint32_t* s, const ushort* gp, int rows,
                                          int w32, size_t gstr, int sstr, int tid) {
  int w4 = w32 >> 2;
  for (int idx = tid; idx < rows * w4; idx += 256) {
    int r = idx / w4, w = idx % w4;
    uint4 v = *(const uint4*)(gp + (size_t)r * gstr + w * 8);
    uint32_t* p = s + r * sstr + w * 4;
    p[0] = v.x; p[1] = v.y; p[2] = v.z; p[3] = v.w;
  }
}

// stage1: acc[nt] = Atile(rows arow..+15) x Btile(cols bcol+nt*8), 3-term split
__device__ __forceinline__ void attn_logits(const uint32_t* sAh, const uint32_t* sAl,
                                            int arow, const uint32_t* sBh,
                                            const uint32_t* sBl, int bcol,
                                            float acc[8][4]) {
  LDSM_SEL;
#pragma unroll
  for (int nt = 0; nt < 8; nt++)
#pragma unroll
    for (int j = 0; j < 4; j++) acc[nt][j] = 0.f;
#pragma unroll
  for (int ks = 0; ks < 4; ks++) {
    uint32_t ah[4], al[4];
    ldsm_x4(ah, s2u(&sAh[(arow + a_row) * 36 + ks * 8 + a_w]));
    ldsm_x4(al, s2u(&sAl[(arow + a_row) * 36 + ks * 8 + a_w]));
#pragma unroll
    for (int ntp = 0; ntp < 4; ntp++) {
      uint32_t bh4[4], bl4[4];
      ldsm_x4(bh4, s2u(&sBh[(bcol + ntp * 16 + b_row) * 36 + ks * 8 + b_w]));
      ldsm_x4(bl4, s2u(&sBl[(bcol + ntp * 16 + b_row) * 36 + ks * 8 + b_w]));
      mma_bf16(acc[ntp * 2], ah, bh4);
      mma_bf16(acc[ntp * 2], ah, bl4);
      mma_bf16(acc[ntp * 2], al, bh4);
      mma_bf16(acc[ntp * 2 + 1], ah, bh4 + 2);
      mma_bf16(acc[ntp * 2 + 1], ah, bl4 + 2);
      mma_bf16(acc[ntp * 2 + 1], al, bh4 + 2);
    }
  }
}
// pack exp'd probabilities (C frags) into A frags (hi/lo)
__device__ __forceinline__ void pack_p(const float p[8][4], uint32_t pah[4][4],
                                       uint32_t pal[4][4]) {
#pragma unroll
  for (int j = 0; j < 4; j++) {
    split2(p[2 * j][0], p[2 * j][1], pah[j][0], pal[j][0]);
    split2(p[2 * j][2], p[2 * j][3], pah[j][1], pal[j][1]);
    split2(p[2 * j + 1][0], p[2 * j + 1][1], pah[j][2], pal[j][2]);
    split2(p[2 * j + 1][2], p[2 * j + 1][3], pah[j][3], pal[j][3]);
  }
}
// stage2: acc[nt] = P(m16 x k64) x B(cols nt*8, k offset koff), 3-term
__device__ __forceinline__ void attn_pv(const uint32_t pah[4][4],
                                        const uint32_t pal[4][4],
                                        const uint32_t* sBh, const uint32_t* sBl,
                                        int bstr, int koff, float acc[8][4]) {
  LDSM_SEL;
  (void)a_row; (void)a_w;
#pragma unroll
  for (int nt = 0; nt < 8; nt++)
#pragma unroll
    for (int j = 0; j < 4; j++) acc[nt][j] = 0.f;
#pragma unroll
  for (int ks = 0; ks < 4; ks++) {
#pragma unroll
    for (int ntp = 0; ntp < 4; ntp++) {
      uint32_t bh4[4], bl4[4];
      ldsm_x4(bh4, s2u(&sBh[(ntp * 16 + b_row) * bstr + koff + ks * 8 + b_w]));
      ldsm_x4(bl4, s2u(&sBl[(ntp * 16 + b_row) * bstr + koff + ks * 8 + b_w]));
      mma_bf16(acc[ntp * 2], pah[ks], bh4);
      mma_bf16(acc[ntp * 2], pah[ks], bl4);
      mma_bf16(acc[ntp * 2], pal[ks], bh4);
      mma_bf16(acc[ntp * 2 + 1], pah[ks], bh4 + 2);
      mma_bf16(acc[ntp * 2 + 1], pah[ks], bl4 + 2);
      mma_bf16(acc[ntp * 2 + 1], pal[ks], bh4 + 2);
    }
  }
}

// ---------------- fp32 -> bf16 hi/lo split (elementwise) ----------------
__global__ __launch_bounds__(256) void conv_split(
    const float4* __restrict__ in, uint2* __restrict__ hi,
    uint2* __restrict__ lo, int n4) {
  int i = blockIdx.x * 256 + threadIdx.x;
  if (i >= n4) return;
  float4 v = in[i];
  uint32_t h0, l0, h1, l1;
  split2(v.x, v.y, h0, l0);
  split2(v.z, v.w, h1, l1);
  hi[i] = make_uint2(h0, h1);
  lo[i] = make_uint2(l0, l1);
}

// ---------------- prep: stacked kvq weights [192][64] hi/lo ----------------
__global__ __launch_bounds__(256) void prep_wkvq(const float* __restrict__ Wk,
                                                 const float* __restrict__ Wv,
                                                 const float* __restrict__ Wq) {
  int i = blockIdx.x * 256 + threadIdx.x;
  if (i >= 192 * 64) return;
  int r = i >> 6, cin = i & 63;
  float w = (r < 64) ? Wk[r * 64 + cin]
            : (r < 128) ? Wv[(r - 64) * 64 + cin] : Wq[(r - 128) * 64 + cin];
  ushort h = bfhi(w);
  g_wkvqh[i] = h;
  g_wkvql[i] = bfhi(w - bfval(h));
}

// ---------------- ctx: kc [bh][s][d], vcT [bh][d][s] hi/lo ----------------
__global__ __launch_bounds__(256) void ctx_proj(
    const float* __restrict__ context, const float* __restrict__ Wck,
    const float* __restrict__ bck, const float* __restrict__ Wcv,
    const float* __restrict__ bcv) {
  __shared__ float sctx[64 * 64];
  int tid = threadIdx.x, bh = blockIdx.x;
  for (int idx = tid; idx < 4096; idx += 256)
    sctx[idx] = context[(size_t)bh * 4096 + idx];
  __syncthreads();
  for (int t = tid; t < 8192; t += 256) {
    int sel = t >> 12;
    int r = t & 4095;
    int s = r >> 6, d = r & 63;
    const float* W = sel ? Wcv : Wck;
    float acc = sel ? bcv[d] : bck[d];
#pragma unroll 8
    for (int c = 0; c < 64; c++) acc += sctx[s * 64 + c] * W[d * 64 + c];
    ushort h = bfhi(acc), l = bfhi(acc - bfval(h));
    if (sel == 0) {
      g_kch[bh * 4096 + s * 64 + d] = h;
      g_kcl[bh * 4096 + s * 64 + d] = l;
    } else {
      g_vcth[bh * 4096 + d * 64 + s] = h;
      g_vctl[bh * 4096 + d * 64 + s] = l;
    }
  }
}

// ---------------- proj GEMM: C = A(32768x512) @ W(512x512)^T + bias ----------------
// SPLITIN: A is f32 (split to hi/lo in-register). SPLITOUT: write hi/lo ushort C.
#define SA_STRIDE 20
template <int SPLITIN, int SPLITOUT>
__global__ __launch_bounds__(256) void mma512(
    const float4* __restrict__ Af,
    const uint4* __restrict__ Ahi, const uint4* __restrict__ Alo,
    const uint4* __restrict__ Bhi, const uint4* __restrict__ Blo,
    const float* __restrict__ bias, float* __restrict__ C,
    ushort* __restrict__ Ch, ushort* __restrict__ Cl) {
  __shared__ uint32_t sA[2][128][SA_STRIDE];
  __shared__ uint32_t sB[2][128][SA_STRIDE];
  int tid = threadIdx.x, wid = tid >> 5, lane = tid & 31;
  int wr = wid >> 1, wc = wid & 1;
  int g = lane >> 2, tg = lane & 3;
  size_t br = (size_t)blockIdx.y * 128;
  int bc = blockIdx.x * 128;

  float acc[2][8][4];
#pragma unroll
  for (int mt = 0; mt < 2; mt++)
#pragma unroll
    for (int nt = 0; nt < 8; nt++)
#pragma unroll
      for (int j = 0; j < 4; j++) acc[mt][nt][j] = 0.f;

  int a_row = lane & 15, a_w = (lane >> 4) * 4;
  int b_row = ((lane >> 4) << 3) + (lane & 7), b_w = ((lane >> 3) & 1) * 4;

  uint4 pre[2][4];
#pragma unroll
  for (int i = 0; i < 2; i++) {
    int idx = tid + i * 256;
    int r = idx >> 2, c4 = idx & 3;
    if (SPLITIN) {
      const float4* src = Af + (br + r) * 128 + c4 * 2;
      float4 f0 = src[0], f1 = src[1];
      split2(f0.x, f0.y, pre[i][0].x, pre[i][1].x);
      split2(f0.z, f0.w, pre[i][0].y, pre[i][1].y);
      split2(f1.x, f1.y, pre[i][0].z, pre[i][1].z);
      split2(f1.z, f1.w, pre[i][0].w, pre[i][1].w);
    } else {
      size_t ga = (br + r) * 64 + c4;
      pre[i][0] = Ahi[ga]; pre[i][1] = Alo[ga];
    }
    size_t gb = ((size_t)bc + r) * 64 + c4;
    pre[i][2] = Bhi[gb]; pre[i][3] = Blo[gb];
  }

  for (int kc = 0; kc < 16; kc++) {
    __syncthreads();
#pragma unroll
    for (int i = 0; i < 2; i++) {
      int idx = tid + i * 256;
      int r = idx >> 2, c4 = idx & 3;
      uint32_t* pa0 = &sA[0][r][c4 * 4];
      uint32_t* pa1 = &sA[1][r][c4 * 4];
      uint32_t* pb0 = &sB[0][r][c4 * 4];
      uint32_t* pb1 = &sB[1][r][c4 * 4];
      pa0[0] = pre[i][0].x; pa0[1] = pre[i][0].y; pa0[2] = pre[i][0].z; pa0[3] = pre[i][0].w;
      pa1[0] = pre[i][1].x; pa1[1] = pre[i][1].y; pa1[2] = pre[i][1].z; pa1[3] = pre[i][1].w;
      pb0[0] = pre[i][2].x; pb0[1] = pre[i][2].y; pb0[2] = pre[i][2].z; pb0[3] = pre[i][2].w;
      pb1[0] = pre[i][3].x; pb1[1] = pre[i][3].y; pb1[2] = pre[i][3].z; pb1[3] = pre[i][3].w;
    }
    __syncthreads();
    if (kc < 15) {
#pragma unroll
      for (int i = 0; i < 2; i++) {
        int idx = tid + i * 256;
        int r = idx >> 2, c4 = idx & 3;
        if (SPLITIN) {
          const float4* src = Af + (br + r) * 128 + (kc + 1) * 8 + c4 * 2;
          float4 f0 = src[0], f1 = src[1];
          split2(f0.x, f0.y, pre[i][0].x, pre[i][1].x);
          split2(f0.z, f0.w, pre[i][0].y, pre[i][1].y);
          split2(f1.x, f1.y, pre[i][0].z, pre[i][1].z);
          split2(f1.z, f1.w, pre[i][0].w, pre[i][1].w);
        } else {
          size_t ga = (br + r) * 64 + (kc + 1) * 4 + c4;
          pre[i][0] = Ahi[ga]; pre[i][1] = Alo[ga];
        }
        size_t gb = ((size_t)bc + r) * 64 + (kc + 1) * 4 + c4;
        pre[i][2] = Bhi[gb]; pre[i][3] = Blo[gb];
      }
    }
#pragma unroll
    for (int ks = 0; ks < 2; ks++) {
      uint32_t af[2][2][4];
#pragma unroll
      for (int h = 0; h < 2; h++)
#pragma unroll
        for (int mt = 0; mt < 2; mt++) {
          int row = wr * 32 + mt * 16 + a_row;
          ldsm_x4(af[h][mt], s2u(&sA[h][row][ks * 8 + a_w]));
        }
      uint32_t bfr[2][8][2];
#pragma unroll
      for (int h = 0; h < 2; h++)
#pragma unroll
        for (int ntp = 0; ntp < 4; ntp++) {
          uint32_t bq[4];
          int col = wc * 64 + ntp * 16 + b_row;
          ldsm_x4(bq, s2u(&sB[h][col][ks * 8 + b_w]));
          bfr[h][ntp * 2][0] = bq[0]; bfr[h][ntp * 2][1] = bq[1];
          bfr[h][ntp * 2 + 1][0] = bq[2]; bfr[h][ntp * 2 + 1][1] = bq[3];
        }
#pragma unroll
      for (int mt = 0; mt < 2; mt++)
#pragma unroll
        for (int nt = 0; nt < 8; nt++) {
          mma_bf16(acc[mt][nt], af[0][mt], bfr[0][nt]);
          mma_bf16(acc[mt][nt], af[0][mt], bfr[1][nt]);
          mma_bf16(acc[mt][nt], af[1][mt], bfr[0][nt]);
        }
    }
  }

#pragma unroll
  for (int mt = 0; mt < 2; mt++) {
    size_t row0 = br + wr * 32 + mt * 16 + g;
#pragma unroll
    for (int nt = 0; nt < 8; nt++) {
      int col = bc + wc * 64 + nt * 8 + tg * 2;
      float bx0 = bias[col], bx1 = bias[col + 1];
      float v0 = acc[mt][nt][0] + bx0, v1 = acc[mt][nt][1] + bx1;
      float v2 = acc[mt][nt][2] + bx0, v3 = acc[mt][nt][3] + bx1;
      if (SPLITOUT) {
        uint32_t hi, lo;
        split2(v0, v1, hi, lo);
        *(uint32_t*)(Ch + row0 * 512 + col) = hi;
        *(uint32_t*)(Cl + row0 * 512 + col) = lo;
        split2(v2, v3, hi, lo);
        *(uint32_t*)(Ch + (row0 + 8) * 512 + col) = hi;
        *(uint32_t*)(Cl + (row0 + 8) * 512 + col) = lo;
      } else {
        *(float2*)&C[row0 * 512 + col] = make_float2(v0, v1);
        *(float2*)&C[(row0 + 8) * 512 + col] = make_float2(v2, v3);
      }
    }
  }
}

// ---------------- fused KVQ + encode: V never leaves the CTA ----------------
#define FXA_H 0
#define FXA_L 4608
#define FW_H  9216
#define FW_L  16128
#define FK_H  0
#define FK_L  4608
#define FVT_H 9216
#define FVT_L 13568
#define FQG_H 17920
#define FQG_L 20224
#define KVQENC_SMEM (23040 * 4)
__global__ __launch_bounds__(256) void kvqenc(const float* __restrict__ bk,
                                              const float* __restrict__ bv,
                                              const float* __restrict__ bq) {
  extern __shared__ uint32_t sm[];
  int tid = threadIdx.x, wid = tid >> 5, lane = tid & 31;
  int g = lane >> 2, tg = lane & 3;
  int wr = wid >> 1, wc = wid & 1;
  int c = blockIdx.x, bh = blockIdx.y, h = bh & 7, b = bh >> 3;
  LDSM_SEL;

  // ---- phase A: kvq GEMM ----
  size_t abase = ((size_t)(b * kN + c * 128)) * 512 + h * 64;
  load_tile(sm + FXA_H, g_xh + abase, 128, 32, 512, 36, tid);
  load_tile(sm + FXA_L, g_xl + abase, 128, 32, 512, 36, tid);
  load_tile(sm + FW_H, g_wkvqh, 192, 32, 64, 36, tid);
  load_tile(sm + FW_L, g_wkvql, 192, 32, 64, 36, tid);
  __syncthreads();

  float kacc[2][12][4];
#pragma unroll
  for (int mt = 0; mt < 2; mt++)
#pragma unroll
    for (int nt = 0; nt < 12; nt++)
#pragma unroll
      for (int j = 0; j < 4; j++) kacc[mt][nt][j] = 0.f;

#pragma unroll
  for (int ks = 0; ks < 4; ks++) {
    uint32_t ah[2][4], al[2][4];
#pragma unroll
    for (int mt = 0; mt < 2; mt++) {
      int row = wr * 32 + mt * 16 + a_row;
      ldsm_x4(ah[mt], s2u(&sm[FXA_H + row * 36 + ks * 8 + a_w]));
      ldsm_x4(al[mt], s2u(&sm[FXA_L + row * 36 + ks * 8 + a_w]));
    }
#pragma unroll
    for (int ntp = 0; ntp < 6; ntp++) {
      uint32_t bh4[4], bl4[4];
      int col = wc * 96 + ntp * 16 + b_row;
      ldsm_x4(bh4, s2u(&sm[FW_H + col * 36 + ks * 8 + b_w]));
      ldsm_x4(bl4, s2u(&sm[FW_L + col * 36 + ks * 8 + b_w]));
#pragma unroll
      for (int mt = 0; mt < 2; mt++) {
        mma_bf16(kacc[mt][ntp * 2], ah[mt], bh4);
        mma_bf16(kacc[mt][ntp * 2], ah[mt], bl4);
        mma_bf16(kacc[mt][ntp * 2], al[mt], bh4);
        mma_bf16(kacc[mt][ntp * 2 + 1], ah[mt], bh4 + 2);
        mma_bf16(kacc[mt][ntp * 2 + 1], ah[mt], bl4 + 2);
        mma_bf16(kacc[mt][ntp * 2 + 1], al[mt], bh4 + 2);
      }
    }
  }
  __syncthreads();  // phase A smem dead; overlay phase B

  // ---- stage K/V into smem, write K/Q to gmem ----
  ushort* svth = (ushort*)(sm + FVT_H);  // [64 d][136]
  ushort* svtl = (ushort*)(sm + FVT_L);
#pragma unroll
  for (int mt = 0; mt < 2; mt++) {
    int tl = wr * 32 + mt * 16 + g;       // local token 0..127
    int tok = c * 128 + tl;
#pragma unroll
    for (int nt = 0; nt < 12; nt++) {
      int col = wc * 96 + nt * 8 + tg * 2;
      int sel = col >> 6, d = col & 63;
      float b0 = (sel == 0) ? bk[d] : (sel == 1) ? bv[d] : bq[d];
      float b1 = (sel == 0) ? bk[d + 1] : (sel == 1) ? bv[d + 1] : bq[d + 1];
      float v0 = kacc[mt][nt][0] + b0, v1 = kacc[mt][nt][1] + b1;
      float v2 = kacc[mt][nt][2] + b0, v3 = kacc[mt][nt][3] + b1;
      if (sel == 1) {                     // V -> smem transposed only
        ushort hh;
        hh = bfhi(v0); svth[d * 136 + tl] = hh;             svtl[d * 136 + tl] = bfhi(v0 - bfval(hh));
        hh = bfhi(v2); svth[d * 136 + tl + 8] = hh;         svtl[d * 136 + tl + 8] = bfhi(v2 - bfval(hh));
        hh = bfhi(v1); svth[(d + 1) * 136 + tl] = hh;       svtl[(d + 1) * 136 + tl] = bfhi(v1 - bfval(hh));
        hh = bfhi(v3); svth[(d + 1) * 136 + tl + 8] = hh;   svtl[(d + 1) * 136 + tl + 8] = bfhi(v3 - bfval(hh));
      } else {
        uint32_t hi, lo, hi2, lo2;
        split2(v0, v1, hi, lo);
        split2(v2, v3, hi2, lo2);
        if (sel == 0) {                   // K -> smem [tok][d] + gmem
          sm[FK_H + tl * 36 + (col >> 1)] = hi;
          sm[FK_L + tl * 36 + (col >> 1)] = lo;
          sm[FK_H + (tl + 8) * 36 + (col >> 1)] = hi2;
          sm[FK_L + (tl + 8) * 36 + (col >> 1)] = lo2;
        }
        ushort* oh = (sel == 0) ? g_kh : g_qh;
        ushort* ol = (sel == 0) ? g_kl : g_ql;
        size_t ob = ((size_t)bh * kN + tok) * 64 + d;
        *(uint32_t*)(oh + ob) = hi; *(uint32_t*)(ol + ob) = lo;
        *(uint32_t*)(oh + ob + 8 * 64) = hi2; *(uint32_t*)(ol + ob + 8 * 64) = lo2;
      }
    }
  }
  load_tile(sm + FQG_H, g_qgh + h * 4096, 64, 32, 64, 36, tid);
  load_tile(sm + FQG_L, g_qgl + h * 4096, 64, 32, 64, 36, tid);
  __syncthreads();

  // ---- phase B: encode logits + P@V ----
  float acc[8][4];
  attn_logits(sm + FQG_H, sm + FQG_L, wr * 16, sm + FK_H, sm + FK_L, wc * 64, acc);
  float s0 = 0.f, s1 = 0.f;
#pragma unroll
  for (int nt = 0; nt < 8; nt++) {
    acc[nt][0] = __expf(acc[nt][0]); acc[nt][1] = __expf(acc[nt][1]);
    acc[nt][2] = __expf(acc[nt][2]); acc[nt][3] = __expf(acc[nt][3]);
    s0 += acc[nt][0] + acc[nt][1];
    s1 += acc[nt][2] + acc[nt][3];
  }
  s0 += __shfl_xor_sync(0xffffffffu, s0, 1);
  s0 += __shfl_xor_sync(0xffffffffu, s0, 2);
  s1 += __shfl_xor_sync(0xffffffffu, s1, 1);
  s1 += __shfl_xor_sync(0xffffffffu, s1, 2);
  int slot = c * 2 + wc;
  if (tg == 0) {
    size_t pb = ((size_t)slot * kBH + bh) * 64 + wr * 16 + g;
    g_psum[pb] = s0;
    g_psum[pb + 8] = s1;
  }
  uint32_t pah[4][4], pal[4][4];
  pack_p(acc, pah, pal);
  attn_pv(pah, pal, sm + FVT_H, sm + FVT_L, 68, wc * 32, acc);
  size_t ab = ((size_t)slot * kBH + bh) * 4096 + (wr * 16 + g) * 64;
#pragma unroll
  for (int nt = 0; nt < 8; nt++) {
    int d = nt * 8 + tg * 2;
    *(float2*)&g_pacc[ab + d] = make_float2(acc[nt][0], acc[nt][1]);
    *(float2*)&g_pacc[ab + 8 * 64 + d] = make_float2(acc[nt][2], acc[nt][3]);
  }
}

// ---------------- encode reduce -> latent^T hi/lo ----------------
__global__ __launch_bounds__(256) void enc_reduce2() {
  __shared__ float sinv[64];
  int tid = threadIdx.x;
  int dchunk = blockIdx.x, bh = blockIdx.y;
  if (tid < 64) {
    float s = 0.f;
    for (int s2 = 0; s2 < kSLOTS; s2++)
      s += g_psum[((size_t)s2 * kBH + bh) * 64 + tid];
    sinv[tid] = 1.f / s;
  }
  __syncthreads();
  for (int idx = tid; idx < 512; idx += 256) {
    int e = dchunk * 512 + idx;
    int m = e >> 6, d = e & 63;
    float a = 0.f;
    for (int s2 = 0; s2 < kSLOTS; s2++)
      a += g_pacc[((size_t)s2 * kBH + bh) * 4096 + e];
    float v = a * sinv[m];
    ushort hh = bfhi(v);
    g_lath[bh * 4096 + d * 64 + m] = hh;
    g_latl[bh * 4096 + d * 64 + m] = bfhi(v - bfval(hh));
  }
}

// ---------------- fused decode-self + cross + gate -> mix hi/lo ----------------
#define TOKH 0
#define TOKL 4608
#define SQGH 9216
#define SQGL 11520
#define SKCH 13824
#define SKCL 16128
#define SLATH 18432
#define SLATL 20736
#define SVCH 23040
#define SVCL 25344
#define DEC_SMEM (27648 * 4)
__global__ __launch_bounds__(256) void dec_fused(const float* __restrict__ smx) {
  extern __shared__ uint32_t sm[];
  int tid = threadIdx.x, wid = tid >> 5, lane = tid & 31;
  int g = lane >> 2, tg = lane & 3;
  int c = blockIdx.x, bh = blockIdx.y, h = bh & 7, b = bh >> 3;
  load_tile(sm + SQGH, g_qgh + h * 4096, 64, 32, 64, 36, tid);
  load_tile(sm + SQGL, g_qgl + h * 4096, 64, 32, 64, 36, tid);
  load_tile(sm + SKCH, g_kch + bh * 4096, 64, 32, 64, 36, tid);
  load_tile(sm + SKCL, g_kcl + bh * 4096, 64, 32, 64, 36, tid);
  load_tile(sm + SLATH, g_lath + bh * 4096, 64, 32, 64, 36, tid);
  load_tile(sm + SLATL, g_latl + bh * 4096, 64, 32, 64, 36, tid);
  load_tile(sm + SVCH, g_vcth + bh * 4096, 64, 32, 64, 36, tid);
  load_tile(sm + SVCL, g_vctl + bh * 4096, 64, 32, 64, 36, tid);
  size_t tokbase = ((size_t)bh * kN + c * 128) * 64;
  load_tile(sm + TOKH, g_kh + tokbase, 128, 32, 64, 36, tid);
  load_tile(sm + TOKL, g_kl + tokbase, 128, 32, 64, 36, tid);
  __syncthreads();
  float wmix = 1.f / (1.f + __expf(-smx[0]));

  float acc[8][4], out[8][4];
  uint32_t pah[4][4], pal[4][4];

  // ---- self: softmax(K . qg) @ latent ----
  attn_logits(sm + TOKH, sm + TOKL, wid * 16, sm + SQGH, sm + SQGL, 0, acc);
  {
    float s0 = 0.f, s1 = 0.f;
#pragma unroll
    for (int nt = 0; nt < 8; nt++) {
      acc[nt][0] = __expf(acc[nt][0]); acc[nt][1] = __expf(acc[nt][1]);
      acc[nt][2] = __expf(acc[nt][2]); acc[nt][3] = __expf(acc[nt][3]);
      s0 += acc[nt][0] + acc[nt][1];
      s1 += acc[nt][2] + acc[nt][3];
    }
    s0 += __shfl_xor_sync(0xffffffffu, s0, 1);
    s0 += __shfl_xor_sync(0xffffffffu, s0, 2);
    s1 += __shfl_xor_sync(0xffffffffu, s1, 1);
    s1 += __shfl_xor_sync(0xffffffffu, s1, 2);
    float w0 = wmix / s0, w1 = wmix / s1;
    pack_p(acc, pah, pal);
    attn_pv(pah, pal, sm + SLATH, sm + SLATL, 36, 0, acc);
#pragma unroll
    for (int nt = 0; nt < 8; nt++) {
      out[nt][0] = w0 * acc[nt][0]; out[nt][1] = w0 * acc[nt][1];
      out[nt][2] = w1 * acc[nt][2]; out[nt][3] = w1 * acc[nt][3];
    }
  }

  // swap token tile: K -> Q
  __syncthreads();
  load_tile(sm + TOKH, g_qh + tokbase, 128, 32, 64, 36, tid);
  load_tile(sm + TOKL, g_ql + tokbase, 128, 32, 64, 36, tid);
  __syncthreads();

  // ---- cross: softmax(Q . kc) @ vc ----
  attn_logits(sm + TOKH, sm + TOKL, wid * 16, sm + SKCH, sm + SKCL, 0, acc);
  {
    float s0 = 0.f, s1 = 0.f;
#pragma unroll
    for (int nt = 0; nt < 8; nt++) {
      acc[nt][0] = __expf(acc[nt][0]); acc[nt][1] = __expf(acc[nt][1]);
      acc[nt][2] = __expf(acc[nt][2]); acc[nt][3] = __expf(acc[nt][3]);
      s0 += acc[nt][0] + acc[nt][1];
      s1 += acc[nt][2] + acc[nt][3];
    }
    s0 += __shfl_xor_sync(0xffffffffu, s0, 1);
    s0 += __shfl_xor_sync(0xffffffffu, s0, 2);
    s1 += __shfl_xor_sync(0xffffffffu, s1, 1);
    s1 += __shfl_xor_sync(0xffffffffu, s1, 2);
    float w0 = (1.f - wmix) / s0, w1 = (1.f - wmix) / s1;
    pack_p(acc, pah, pal);
    attn_pv(pah, pal, sm + SVCH, sm + SVCL, 36, 0, acc);
#pragma unroll
    for (int nt = 0; nt < 8; nt++) {
      out[nt][0] += w0 * acc[nt][0]; out[nt][1] += w0 * acc[nt][1];
      out[nt][2] += w1 * acc[nt][2]; out[nt][3] += w1 * acc[nt][3];
    }
  }

  // write mix hi/lo
  int tok0 = c * 128 + wid * 16 + g;
#pragma unroll
  for (int nt = 0; nt < 8; nt++) {
    int col = h * 64 + nt * 8 + tg * 2;
    size_t a0 = ((size_t)(b * kN + tok0)) * 512 + col;
    uint32_t hi, lo;
    split2(out[nt][0], out[nt][1], hi, lo);
    *(uint32_t*)(g_mixh + a0) = hi;
    *(uint32_t*)(g_mixl + a0) = lo;
    split2(out[nt][2], out[nt][3], hi, lo);
    *(uint32_t*)(g_mixh + a0 + 8 * 512) = hi;
    *(uint32_t*)(g_mixl + a0 + 8 * 512) = lo;
  }
}

// ---------------- launch ----------------
extern "C" void kernel_launch(void* const* d_in, const int* in_sizes, int n_in,
                              void* d_out, int out_size) {
  const float* x    = (const float*)d_in[0];
  const float* ctx  = (const float*)d_in[1];
  const float* qg   = (const float*)d_in[2];
  const float* Wx   = (const float*)d_in[3];
  const float* bx   = (const float*)d_in[4];
  const float* Wk   = (const float*)d_in[5];
  const float* bk   = (const float*)d_in[6];
  const float* Wv   = (const float*)d_in[7];
  const float* bv   = (const float*)d_in[8];
  const float* Wcq  = (const float*)d_in[9];
  const float* bcq  = (const float*)d_in[10];
  const float* Wck  = (const float*)d_in[11];
  const float* bck  = (const float*)d_in[12];
  const float* Wcv  = (const float*)d_in[13];
  const float* bcv  = (const float*)d_in[14];
  const float* smx  = (const float*)d_in[15];
  const float* Wo   = (const float*)d_in[16];
  const float* bo   = (const float*)d_in[17];
  float* out = (float*)d_out;

  void *whi_p, *wlo_p, *xh_p, *xl_p, *mh_p, *ml_p, *qgh_p, *qgl_p;
  cudaGetSymbolAddress(&whi_p, g_whi);
  cudaGetSymbolAddress(&wlo_p, g_wlo);
  cudaGetSymbolAddress(&xh_p, g_xh);
  cudaGetSymbolAddress(&xl_p, g_xl);
  cudaGetSymbolAddress(&mh_p, g_mixh);
  cudaGetSymbolAddress(&ml_p, g_mixl);
  cudaGetSymbolAddress(&qgh_p, g_qgh);
  cudaGetSymbolAddress(&qgl_p, g_qgl);

  cudaFuncSetAttribute(kvqenc, cudaFuncAttributeMaxDynamicSharedMemorySize,
                       KVQENC_SMEM);
  cudaFuncSetAttribute(dec_fused, cudaFuncAttributeMaxDynamicSharedMemorySize,
                       DEC_SMEM);

  const int nW4 = kDIM * kDIM / 4;

  // order chosen so launch #4 (the ncu-captured slot) is proj1's mma512
  ctx_proj<<<kBH, 256>>>(ctx, Wck, bck, Wcv, bcv);
  conv_split<<<nW4 / 256, 256>>>((const float4*)Wx, (uint2*)whi_p, (uint2*)wlo_p, nW4);
  prep_wkvq<<<48, 256>>>(Wk, Wv, Wcq);
  // proj1: xmid = x @ Wx^T + bx  (f32 A split in-kernel) -> hi/lo
  mma512<1, 1><<<dim3(4, kROWS / 128), 256>>>(
      (const float4*)x, nullptr, nullptr, (const uint4*)whi_p,
      (const uint4*)wlo_p, bx, nullptr, (ushort*)xh_p, (ushort*)xl_p);
  conv_split<<<32, 256>>>((const float4*)qg, (uint2*)qgh_p, (uint2*)qgl_p, 8192);

  // fused kvq + encode, then reduce, then fused decode
  kvqenc<<<dim3(128, kBH), 256, KVQENC_SMEM>>>(bk, bv, bcq);
  enc_reduce2<<<dim3(8, kBH), 256>>>();
  dec_fused<<<dim3(128, kBH), 256, DEC_SMEM>>>(smx);

  // proj2: out = mix @ Wo^T + bo
  conv_split<<<nW4 / 256, 256>>>((const float4*)Wo, (uint2*)whi_p, (uint2*)wlo_p, nW4);
  mma512<0, 0><<<dim3(4, kROWS / 128), 256>>>(
      nullptr, (const uint4*)mh_p, (const uint4*)ml_p, (const uint4*)whi_p,
      (const uint4*)wlo_p, bo, out, nullptr, nullptr);
}

// round 10
// speedup vs baseline: 1.0195x; 1.0195x over previous
#include <cuda_runtime.h>
#include <cuda_bf16.h>
#include <cstdint>

// ---------------- problem constants ----------------
#define kB   2
#define kN   16384
#define kDIM 512
#define kH   8
#define kROWS (kB * kN)          // 32768
#define kBH   (kB * kH)          // 16
#define kSLOTS 256               // enc partial slots (128 chunks x 2 warp-halves)

// ---------------- scratch (device globals) ----------------
__device__ ushort g_xh[kROWS * kDIM],  g_xl[kROWS * kDIM];      // xmid hi/lo
__device__ ushort g_mixh[kROWS * kDIM], g_mixl[kROWS * kDIM];   // gated mix hi/lo
__device__ ushort g_kh[kBH * kN * 64], g_kl[kBH * kN * 64];
__device__ ushort g_qh[kBH * kN * 64], g_ql[kBH * kN * 64];
__device__ ushort g_qgh[512 * 64], g_qgl[512 * 64];             // [h*64+m][d]
__device__ ushort g_kch[kBH * 4096], g_kcl[kBH * 4096];         // [bh][s][d]
__device__ ushort g_vcth[kBH * 4096], g_vctl[kBH * 4096];       // [bh][d][s]
__device__ ushort g_lath[kBH * 4096], g_latl[kBH * 4096];       // latent^T [bh][d][m]
__device__ ushort g_wkvqh[192 * 64], g_wkvql[192 * 64];         // [col(k|v|q)][din]
__device__ ushort g_ahi[kROWS * kDIM], g_alo[kROWS * kDIM];     // proj A split (x)
__device__ ushort g_whi[kDIM * kDIM], g_wlo[kDIM * kDIM];       // proj W split
__device__ float  g_psum[kSLOTS * kBH * 64];
__device__ float  g_pacc[(size_t)kSLOTS * kBH * 4096];          // 67 MB

// ---------------- helpers ----------------
__device__ __forceinline__ ushort bfhi(float x) {
  return __bfloat16_as_ushort(__float2bfloat16(x));
}
__device__ __forceinline__ float bfval(ushort u) {
  return __bfloat162float(__ushort_as_bfloat16(u));
}
__device__ __forceinline__ void split2(float a, float b, uint32_t& hi, uint32_t& lo) {
  ushort ha = bfhi(a), hb = bfhi(b);
  hi = (uint32_t)ha | ((uint32_t)hb << 16);
  lo = (uint32_t)bfhi(a - bfval(ha)) | ((uint32_t)bfhi(b - bfval(hb)) << 16);
}
__device__ __forceinline__ void mma_bf16(float* d, const uint32_t* a,
                                         const uint32_t* b) {
  asm volatile(
      "mma.sync.aligned.m16n8k16.row.col.f32.bf16.bf16.f32 "
      "{%0,%1,%2,%3}, {%4,%5,%6,%7}, {%8,%9}, {%0,%1,%2,%3};"
      : "+f"(d[0]), "+f"(d[1]), "+f"(d[2]), "+f"(d[3])
      : "r"(a[0]), "r"(a[1]), "r"(a[2]), "r"(a[3]), "r"(b[0]), "r"(b[1]));
}
__device__ __forceinline__ uint32_t s2u(const void* p) {
  return (uint32_t)__cvta_generic_to_shared(p);
}
__device__ __forceinline__ void ldsm_x4(uint32_t* r, uint32_t addr) {
  asm volatile(
      "ldmatrix.sync.aligned.m8n8.x4.shared.b16 {%0,%1,%2,%3}, [%4];"
      : "=r"(r[0]), "=r"(r[1]), "=r"(r[2]), "=r"(r[3]) : "r"(addr));
}
// ldmatrix lane selectors (validated mapping, rel_err-identical)
#define LDSM_SEL                                            \
  int lane_ = threadIdx.x & 31;                             \
  int a_row = lane_ & 15, a_w = (lane_ >> 4) * 4;           \
  int b_row = ((lane_ >> 4) << 3) + (lane_ & 7);            \
  int b_w = ((lane_ >> 3) & 1) * 4;

// load R rows x (w32 uint32) bf16 tile from gmem into smem with row stride sstr
__device__ __forceinline__ void load_tile(uint32_t* s, const ushort* gp, int rows,
                                          int w32, size_t gstr, int sstr, int tid) {
  int w4 = w32 >> 2;
  for (int idx = tid; idx < rows * w4; idx += 256) {
    int r = idx / w4, w = idx % w4;
    uint4 v = *(const uint4*)(gp + (size_t)r * gstr + w * 8);
    uint32_t* p = s + r * sstr + w * 4;
    p[0] = v.x; p[1] = v.y; p[2] = v.z; p[3] = v.w;
  }
}

// stage1: acc[nt] = Atile(rows arow..+15) x Btile(cols bcol+nt*8), 3-term split
__device__ __forceinline__ void attn_logits(const uint32_t* sAh, const uint32_t* sAl,
                                            int arow, const uint32_t* sBh,
                                            const uint32_t* sBl, int bcol,
                                            float acc[8][4]) {
  LDSM_SEL;
#pragma unroll
  for (int nt = 0; nt < 8; nt++)
#pragma unroll
    for (int j = 0; j < 4; j++) acc[nt][j] = 0.f;
#pragma unroll
  for (int ks = 0; ks < 4; ks++) {
    uint32_t ah[4], al[4];
    ldsm_x4(ah, s2u(&sAh[(arow + a_row) * 36 + ks * 8 + a_w]));
    ldsm_x4(al, s2u(&sAl[(arow + a_row) * 36 + ks * 8 + a_w]));
#pragma unroll
    for (int ntp = 0; ntp < 4; ntp++) {
      uint32_t bh4[4], bl4[4];
      ldsm_x4(bh4, s2u(&sBh[(bcol + ntp * 16 + b_row) * 36 + ks * 8 + b_w]));
      ldsm_x4(bl4, s2u(&sBl[(bcol + ntp * 16 + b_row) * 36 + ks * 8 + b_w]));
      mma_bf16(acc[ntp * 2], ah, bh4);
      mma_bf16(acc[ntp * 2], ah, bl4);
      mma_bf16(acc[ntp * 2], al, bh4);
      mma_bf16(acc[ntp * 2 + 1], ah, bh4 + 2);
      mma_bf16(acc[ntp * 2 + 1], ah, bl4 + 2);
      mma_bf16(acc[ntp * 2 + 1], al, bh4 + 2);
    }
  }
}
// pack exp'd probabilities (C frags) into A frags (hi/lo)
__device__ __forceinline__ void pack_p(const float p[8][4], uint32_t pah[4][4],
                                       uint32_t pal[4][4]) {
#pragma unroll
  for (int j = 0; j < 4; j++) {
    split2(p[2 * j][0], p[2 * j][1], pah[j][0], pal[j][0]);
    split2(p[2 * j][2], p[2 * j][3], pah[j][1], pal[j][1]);
    split2(p[2 * j + 1][0], p[2 * j + 1][1], pah[j][2], pal[j][2]);
    split2(p[2 * j + 1][2], p[2 * j + 1][3], pah[j][3], pal[j][3]);
  }
}
// stage2: acc[nt] = P(m16 x k64) x B(cols nt*8, k offset koff), 3-term
__device__ __forceinline__ void attn_pv(const uint32_t pah[4][4],
                                        const uint32_t pal[4][4],
                                        const uint32_t* sBh, const uint32_t* sBl,
                                        int bstr, int koff, float acc[8][4]) {
  LDSM_SEL;
  (void)a_row; (void)a_w;
#pragma unroll
  for (int nt = 0; nt < 8; nt++)
#pragma unroll
    for (int j = 0; j < 4; j++) acc[nt][j] = 0.f;
#pragma unroll
  for (int ks = 0; ks < 4; ks++) {
#pragma unroll
    for (int ntp = 0; ntp < 4; ntp++) {
      uint32_t bh4[4], bl4[4];
      ldsm_x4(bh4, s2u(&sBh[(ntp * 16 + b_row) * bstr + koff + ks * 8 + b_w]));
      ldsm_x4(bl4, s2u(&sBl[(ntp * 16 + b_row) * bstr + koff + ks * 8 + b_w]));
      mma_bf16(acc[ntp * 2], pah[ks], bh4);
      mma_bf16(acc[ntp * 2], pah[ks], bl4);
      mma_bf16(acc[ntp * 2], pal[ks], bh4);
      mma_bf16(acc[ntp * 2 + 1], pah[ks], bh4 + 2);
      mma_bf16(acc[ntp * 2 + 1], pah[ks], bl4 + 2);
      mma_bf16(acc[ntp * 2 + 1], pal[ks], bh4 + 2);
    }
  }
}

// ---------------- conv2: split x AND Wx in one launch ----------------
__global__ __launch_bounds__(256) void conv2(
    const float4* __restrict__ in0, uint2* __restrict__ hi0,
    uint2* __restrict__ lo0, int nb0,
    const float4* __restrict__ in1, uint2* __restrict__ hi1,
    uint2* __restrict__ lo1) {
  int b = blockIdx.x;
  const float4* in; uint2 *hi, *lo; int i;
  if (b < nb0) { in = in0; hi = hi0; lo = lo0; i = b * 256 + threadIdx.x; }
  else { in = in1; hi = hi1; lo = lo1; i = (b - nb0) * 256 + threadIdx.x; }
  float4 v = in[i];
  uint32_t h0, l0, h1, l1;
  split2(v.x, v.y, h0, l0);
  split2(v.z, v.w, h1, l1);
  hi[i] = make_uint2(h0, h1);
  lo[i] = make_uint2(l0, l1);
}

// ---------------- conv_split (single-tensor variant, for Wo) ----------------
__global__ __launch_bounds__(256) void conv_split(
    const float4* __restrict__ in, uint2* __restrict__ hi,
    uint2* __restrict__ lo, int n4) {
  int i = blockIdx.x * 256 + threadIdx.x;
  if (i >= n4) return;
  float4 v = in[i];
  uint32_t h0, l0, h1, l1;
  split2(v.x, v.y, h0, l0);
  split2(v.z, v.w, h1, l1);
  hi[i] = make_uint2(h0, h1);
  lo[i] = make_uint2(l0, l1);
}

// ---------------- prep_small: ctx_proj (16) + wkvq split (48) + qg split (32) ----------------
__global__ __launch_bounds__(256) void prep_small(
    const float* __restrict__ context, const float* __restrict__ Wck,
    const float* __restrict__ bck, const float* __restrict__ Wcv,
    const float* __restrict__ bcv, const float* __restrict__ Wk,
    const float* __restrict__ Wv, const float* __restrict__ Wq,
    const float4* __restrict__ qg) {
  __shared__ float sctx[64 * 64];
  int tid = threadIdx.x, bid = blockIdx.x;
  if (bid < 16) {
    int bh = bid;
    for (int idx = tid; idx < 4096; idx += 256)
      sctx[idx] = context[(size_t)bh * 4096 + idx];
    __syncthreads();
    for (int t = tid; t < 8192; t += 256) {
      int sel = t >> 12;
      int r = t & 4095;
      int s = r >> 6, d = r & 63;
      const float* W = sel ? Wcv : Wck;
      float acc = sel ? bcv[d] : bck[d];
#pragma unroll 8
      for (int c = 0; c < 64; c++) acc += sctx[s * 64 + c] * W[d * 64 + c];
      ushort h = bfhi(acc), l = bfhi(acc - bfval(h));
      if (sel == 0) {
        g_kch[bh * 4096 + s * 64 + d] = h;
        g_kcl[bh * 4096 + s * 64 + d] = l;
      } else {
        g_vcth[bh * 4096 + d * 64 + s] = h;
        g_vctl[bh * 4096 + d * 64 + s] = l;
      }
    }
  } else if (bid < 64) {
    int i = (bid - 16) * 256 + tid;   // < 12288
    int r = i >> 6, cin = i & 63;
    float w = (r < 64) ? Wk[r * 64 + cin]
              : (r < 128) ? Wv[(r - 64) * 64 + cin] : Wq[(r - 128) * 64 + cin];
    ushort h = bfhi(w);
    g_wkvqh[i] = h;
    g_wkvql[i] = bfhi(w - bfval(h));
  } else {
    int i = (bid - 64) * 256 + tid;   // < 8192 float4s
    float4 v = qg[i];
    uint32_t h0, l0, h1, l1;
    split2(v.x, v.y, h0, l0);
    split2(v.z, v.w, h1, l1);
    ((uint2*)g_qgh)[i] = make_uint2(h0, h1);
    ((uint2*)g_qgl)[i] = make_uint2(l0, l1);
  }
}

// ---------------- proj GEMM: C = A(32768x512) @ W(512x512)^T + bias ----------------
// 2 CTAs/SM target (regs<=128); no register prefetch (occupancy hides latency).
#define SA_STRIDE 20
template <int SPLITOUT>
__global__ __launch_bounds__(256, 2) void mma512(
    const uint4* __restrict__ Ahi, const uint4* __restrict__ Alo,
    const uint4* __restrict__ Bhi, const uint4* __restrict__ Blo,
    const float* __restrict__ bias, float* __restrict__ C,
    ushort* __restrict__ Ch, ushort* __restrict__ Cl) {
  __shared__ uint32_t sA[2][128][SA_STRIDE];
  __shared__ uint32_t sB[2][128][SA_STRIDE];
  int tid = threadIdx.x, wid = tid >> 5, lane = tid & 31;
  int wr = wid >> 1, wc = wid & 1;
  int g = lane >> 2, tg = lane & 3;
  size_t br = (size_t)blockIdx.y * 128;
  int bc = blockIdx.x * 128;

  float acc[2][8][4];
#pragma unroll
  for (int mt = 0; mt < 2; mt++)
#pragma unroll
    for (int nt = 0; nt < 8; nt++)
#pragma unroll
      for (int j = 0; j < 4; j++) acc[mt][nt][j] = 0.f;

  int a_row = lane & 15, a_w = (lane >> 4) * 4;
  int b_row = ((lane >> 4) << 3) + (lane & 7), b_w = ((lane >> 3) & 1) * 4;

  for (int kc = 0; kc < 16; kc++) {
    __syncthreads();
#pragma unroll
    for (int i = 0; i < 2; i++) {
      int idx = tid + i * 256;
      int r = idx >> 2, c4 = idx & 3;
      size_t ga = (br + r) * 64 + kc * 4 + c4;
      size_t gb = ((size_t)bc + r) * 64 + kc * 4 + c4;
      uint4 va0 = Ahi[ga], va1 = Alo[ga], vb0 = Bhi[gb], vb1 = Blo[gb];
      uint32_t* pa0 = &sA[0][r][c4 * 4];
      uint32_t* pa1 = &sA[1][r][c4 * 4];
      uint32_t* pb0 = &sB[0][r][c4 * 4];
      uint32_t* pb1 = &sB[1][r][c4 * 4];
      pa0[0] = va0.x; pa0[1] = va0.y; pa0[2] = va0.z; pa0[3] = va0.w;
      pa1[0] = va1.x; pa1[1] = va1.y; pa1[2] = va1.z; pa1[3] = va1.w;
      pb0[0] = vb0.x; pb0[1] = vb0.y; pb0[2] = vb0.z; pb0[3] = vb0.w;
      pb1[0] = vb1.x; pb1[1] = vb1.y; pb1[2] = vb1.z; pb1[3] = vb1.w;
    }
    __syncthreads();
#pragma unroll
    for (int ks = 0; ks < 2; ks++) {
      uint32_t af[2][2][4];
#pragma unroll
      for (int h = 0; h < 2; h++)
#pragma unroll
        for (int mt = 0; mt < 2; mt++) {
          int row = wr * 32 + mt * 16 + a_row;
          ldsm_x4(af[h][mt], s2u(&sA[h][row][ks * 8 + a_w]));
        }
      uint32_t bfr[2][8][2];
#pragma unroll
      for (int h = 0; h < 2; h++)
#pragma unroll
        for (int ntp = 0; ntp < 4; ntp++) {
          uint32_t bq[4];
          int col = wc * 64 + ntp * 16 + b_row;
          ldsm_x4(bq, s2u(&sB[h][col][ks * 8 + b_w]));
          bfr[h][ntp * 2][0] = bq[0]; bfr[h][ntp * 2][1] = bq[1];
          bfr[h][ntp * 2 + 1][0] = bq[2]; bfr[h][ntp * 2 + 1][1] = bq[3];
        }
#pragma unroll
      for (int mt = 0; mt < 2; mt++)
#pragma unroll
        for (int nt = 0; nt < 8; nt++) {
          mma_bf16(acc[mt][nt], af[0][mt], bfr[0][nt]);
          mma_bf16(acc[mt][nt], af[0][mt], bfr[1][nt]);
          mma_bf16(acc[mt][nt], af[1][mt], bfr[0][nt]);
        }
    }
  }

#pragma unroll
  for (int mt = 0; mt < 2; mt++) {
    size_t row0 = br + wr * 32 + mt * 16 + g;
#pragma unroll
    for (int nt = 0; nt < 8; nt++) {
      int col = bc + wc * 64 + nt * 8 + tg * 2;
      float bx0 = bias[col], bx1 = bias[col + 1];
      float v0 = acc[mt][nt][0] + bx0, v1 = acc[mt][nt][1] + bx1;
      float v2 = acc[mt][nt][2] + bx0, v3 = acc[mt][nt][3] + bx1;
      if (SPLITOUT) {
        uint32_t hi, lo;
        split2(v0, v1, hi, lo);
        *(uint32_t*)(Ch + row0 * 512 + col) = hi;
        *(uint32_t*)(Cl + row0 * 512 + col) = lo;
        split2(v2, v3, hi, lo);
        *(uint32_t*)(Ch + (row0 + 8) * 512 + col) = hi;
        *(uint32_t*)(Cl + (row0 + 8) * 512 + col) = lo;
      } else {
        *(float2*)&C[row0 * 512 + col] = make_float2(v0, v1);
        *(float2*)&C[(row0 + 8) * 512 + col] = make_float2(v2, v3);
      }
    }
  }
}

// ---------------- fused KVQ + encode: V never leaves the CTA ----------------
#define FXA_H 0
#define FXA_L 4608
#define FW_H  9216
#define FW_L  16128
#define FK_H  0
#define FK_L  4608
#define FVT_H 9216
#define FVT_L 13568
#define FQG_H 17920
#define FQG_L 20224
#define KVQENC_SMEM (23040 * 4)
__global__ __launch_bounds__(256) void kvqenc(const float* __restrict__ bk,
                                              const float* __restrict__ bv,
                                              const float* __restrict__ bq) {
  extern __shared__ uint32_t sm[];
  int tid = threadIdx.x, wid = tid >> 5, lane = tid & 31;
  int g = lane >> 2, tg = lane & 3;
  int wr = wid >> 1, wc = wid & 1;
  int c = blockIdx.x, bh = blockIdx.y, h = bh & 7, b = bh >> 3;
  LDSM_SEL;

  // ---- phase A: kvq GEMM ----
  size_t abase = ((size_t)(b * kN + c * 128)) * 512 + h * 64;
  load_tile(sm + FXA_H, g_xh + abase, 128, 32, 512, 36, tid);
  load_tile(sm + FXA_L, g_xl + abase, 128, 32, 512, 36, tid);
  load_tile(sm + FW_H, g_wkvqh, 192, 32, 64, 36, tid);
  load_tile(sm + FW_L, g_wkvql, 192, 32, 64, 36, tid);
  __syncthreads();

  float kacc[2][12][4];
#pragma unroll
  for (int mt = 0; mt < 2; mt++)
#pragma unroll
    for (int nt = 0; nt < 12; nt++)
#pragma unroll
      for (int j = 0; j < 4; j++) kacc[mt][nt][j] = 0.f;

#pragma unroll
  for (int ks = 0; ks < 4; ks++) {
    uint32_t ah[2][4], al[2][4];
#pragma unroll
    for (int mt = 0; mt < 2; mt++) {
      int row = wr * 32 + mt * 16 + a_row;
      ldsm_x4(ah[mt], s2u(&sm[FXA_H + row * 36 + ks * 8 + a_w]));
      ldsm_x4(al[mt], s2u(&sm[FXA_L + row * 36 + ks * 8 + a_w]));
    }
#pragma unroll
    for (int ntp = 0; ntp < 6; ntp++) {
      uint32_t bh4[4], bl4[4];
      int col = wc * 96 + ntp * 16 + b_row;
      ldsm_x4(bh4, s2u(&sm[FW_H + col * 36 + ks * 8 + b_w]));
      ldsm_x4(bl4, s2u(&sm[FW_L + col * 36 + ks * 8 + b_w]));
#pragma unroll
      for (int mt = 0; mt < 2; mt++) {
        mma_bf16(kacc[mt][ntp * 2], ah[mt], bh4);
        mma_bf16(kacc[mt][ntp * 2], ah[mt], bl4);
        mma_bf16(kacc[mt][ntp * 2], al[mt], bh4);
        mma_bf16(kacc[mt][ntp * 2 + 1], ah[mt], bh4 + 2);
        mma_bf16(kacc[mt][ntp * 2 + 1], ah[mt], bl4 + 2);
        mma_bf16(kacc[mt][ntp * 2 + 1], al[mt], bh4 + 2);
      }
    }
  }
  __syncthreads();  // phase A smem dead; overlay phase B

  // ---- stage K/V into smem, write K/Q to gmem ----
  ushort* svth = (ushort*)(sm + FVT_H);  // [64 d][136]
  ushort* svtl = (ushort*)(sm + FVT_L);
#pragma unroll
  for (int mt = 0; mt < 2; mt++) {
    int tl = wr * 32 + mt * 16 + g;       // local token 0..127
    int tok = c * 128 + tl;
#pragma unroll
    for (int nt = 0; nt < 12; nt++) {
      int col = wc * 96 + nt * 8 + tg * 2;
      int sel = col >> 6, d = col & 63;
      float b0 = (sel == 0) ? bk[d] : (sel == 1) ? bv[d] : bq[d];
      float b1 = (sel == 0) ? bk[d + 1] : (sel == 1) ? bv[d + 1] : bq[d + 1];
      float v0 = kacc[mt][nt][0] + b0, v1 = kacc[mt][nt][1] + b1;
      float v2 = kacc[mt][nt][2] + b0, v3 = kacc[mt][nt][3] + b1;
      if (sel == 1) {                     // V -> smem transposed only
        ushort hh;
        hh = bfhi(v0); svth[d * 136 + tl] = hh;             svtl[d * 136 + tl] = bfhi(v0 - bfval(hh));
        hh = bfhi(v2); svth[d * 136 + tl + 8] = hh;         svtl[d * 136 + tl + 8] = bfhi(v2 - bfval(hh));
        hh = bfhi(v1); svth[(d + 1) * 136 + tl] = hh;       svtl[(d + 1) * 136 + tl] = bfhi(v1 - bfval(hh));
        hh = bfhi(v3); svth[(d + 1) * 136 + tl + 8] = hh;   svtl[(d + 1) * 136 + tl + 8] = bfhi(v3 - bfval(hh));
      } else {
        uint32_t hi, lo, hi2, lo2;
        split2(v0, v1, hi, lo);
        split2(v2, v3, hi2, lo2);
        if (sel == 0) {                   // K -> smem [tok][d] + gmem
          sm[FK_H + tl * 36 + (col >> 1)] = hi;
          sm[FK_L + tl * 36 + (col >> 1)] = lo;
          sm[FK_H + (tl + 8) * 36 + (col >> 1)] = hi2;
          sm[FK_L + (tl + 8) * 36 + (col >> 1)] = lo2;
        }
        ushort* oh = (sel == 0) ? g_kh : g_qh;
        ushort* ol = (sel == 0) ? g_kl : g_ql;
        size_t ob = ((size_t)bh * kN + tok) * 64 + d;
        *(uint32_t*)(oh + ob) = hi; *(uint32_t*)(ol + ob) = lo;
        *(uint32_t*)(oh + ob + 8 * 64) = hi2; *(uint32_t*)(ol + ob + 8 * 64) = lo2;
      }
    }
  }
  load_tile(sm + FQG_H, g_qgh + h * 4096, 64, 32, 64, 36, tid);
  load_tile(sm + FQG_L, g_qgl + h * 4096, 64, 32, 64, 36, tid);
  __syncthreads();

  // ---- phase B: encode logits + P@V ----
  float acc[8][4];
  attn_logits(sm + FQG_H, sm + FQG_L, wr * 16, sm + FK_H, sm + FK_L, wc * 64, acc);
  float s0 = 0.f, s1 = 0.f;
#pragma unroll
  for (int nt = 0; nt < 8; nt++) {
    acc[nt][0] = __expf(acc[nt][0]); acc[nt][1] = __expf(acc[nt][1]);
    acc[nt][2] = __expf(acc[nt][2]); acc[nt][3] = __expf(acc[nt][3]);
    s0 += acc[nt][0] + acc[nt][1];
    s1 += acc[nt][2] + acc[nt][3];
  }
  s0 += __shfl_xor_sync(0xffffffffu, s0, 1);
  s0 += __shfl_xor_sync(0xffffffffu, s0, 2);
  s1 += __shfl_xor_sync(0xffffffffu, s1, 1);
  s1 += __shfl_xor_sync(0xffffffffu, s1, 2);
  int slot = c * 2 + wc;
  if (tg == 0) {
    size_t pb = ((size_t)slot * kBH + bh) * 64 + wr * 16 + g;
    g_psum[pb] = s0;
    g_psum[pb + 8] = s1;
  }
  uint32_t pah[4][4], pal[4][4];
  pack_p(acc, pah, pal);
  attn_pv(pah, pal, sm + FVT_H, sm + FVT_L, 68, wc * 32, acc);
  size_t ab = ((size_t)slot * kBH + bh) * 4096 + (wr * 16 + g) * 64;
#pragma unroll
  for (int nt = 0; nt < 8; nt++) {
    int d = nt * 8 + tg * 2;
    *(float2*)&g_pacc[ab + d] = make_float2(acc[nt][0], acc[nt][1]);
    *(float2*)&g_pacc[ab + 8 * 64 + d] = make_float2(acc[nt][2], acc[nt][3]);
  }
}

// ---------------- encode reduce -> latent^T hi/lo ----------------
__global__ __launch_bounds__(256) void enc_reduce2() {
  __shared__ float sinv[64];
  int tid = threadIdx.x;
  int dchunk = blockIdx.x, bh = blockIdx.y;
  if (tid < 64) {
    float s = 0.f;
    for (int s2 = 0; s2 < kSLOTS; s2++)
      s += g_psum[((size_t)s2 * kBH + bh) * 64 + tid];
    sinv[tid] = 1.f / s;
  }
  __syncthreads();
  for (int idx = tid; idx < 512; idx += 256) {
    int e = dchunk * 512 + idx;
    int m = e >> 6, d = e & 63;
    float a = 0.f;
    for (int s2 = 0; s2 < kSLOTS; s2++)
      a += g_pacc[((size_t)s2 * kBH + bh) * 4096 + e];
    float v = a * sinv[m];
    ushort hh = bfhi(v);
    g_lath[bh * 4096 + d * 64 + m] = hh;
    g_latl[bh * 4096 + d * 64 + m] = bfhi(v - bfval(hh));
  }
}

// ---------------- fused decode-self + cross + gate -> mix hi/lo ----------------
#define TOKH 0
#define TOKL 4608
#define SQGH 9216
#define SQGL 11520
#define SKCH 13824
#define SKCL 16128
#define SLATH 18432
#define SLATL 20736
#define SVCH 23040
#define SVCL 25344
#define DEC_SMEM (27648 * 4)
__global__ __launch_bounds__(256) void dec_fused(const float* __restrict__ smx) {
  extern __shared__ uint32_t sm[];
  int tid = threadIdx.x, wid = tid >> 5, lane = tid & 31;
  int g = lane >> 2, tg = lane & 3;
  int c = blockIdx.x, bh = blockIdx.y, h = bh & 7, b = bh >> 3;
  load_tile(sm + SQGH, g_qgh + h * 4096, 64, 32, 64, 36, tid);
  load_tile(sm + SQGL, g_qgl + h * 4096, 64, 32, 64, 36, tid);
  load_tile(sm + SKCH, g_kch + bh * 4096, 64, 32, 64, 36, tid);
  load_tile(sm + SKCL, g_kcl + bh * 4096, 64, 32, 64, 36, tid);
  load_tile(sm + SLATH, g_lath + bh * 4096, 64, 32, 64, 36, tid);
  load_tile(sm + SLATL, g_latl + bh * 4096, 64, 32, 64, 36, tid);
  load_tile(sm + SVCH, g_vcth + bh * 4096, 64, 32, 64, 36, tid);
  load_tile(sm + SVCL, g_vctl + bh * 4096, 64, 32, 64, 36, tid);
  size_t tokbase = ((size_t)bh * kN + c * 128) * 64;
  load_tile(sm + TOKH, g_kh + tokbase, 128, 32, 64, 36, tid);
  load_tile(sm + TOKL, g_kl + tokbase, 128, 32, 64, 36, tid);
  __syncthreads();
  float wmix = 1.f / (1.f + __expf(-smx[0]));

  float acc[8][4], out[8][4];
  uint32_t pah[4][4], pal[4][4];

  // ---- self: softmax(K . qg) @ latent ----
  attn_logits(sm + TOKH, sm + TOKL, wid * 16, sm + SQGH, sm + SQGL, 0, acc);
  {
    float s0 = 0.f, s1 = 0.f;
#pragma unroll
    for (int nt = 0; nt < 8; nt++) {
      acc[nt][0] = __expf(acc[nt][0]); acc[nt][1] = __expf(acc[nt][1]);
      acc[nt][2] = __expf(acc[nt][2]); acc[nt][3] = __expf(acc[nt][3]);
      s0 += acc[nt][0] + acc[nt][1];
      s1 += acc[nt][2] + acc[nt][3];
    }
    s0 += __shfl_xor_sync(0xffffffffu, s0, 1);
    s0 += __shfl_xor_sync(0xffffffffu, s0, 2);
    s1 += __shfl_xor_sync(0xffffffffu, s1, 1);
    s1 += __shfl_xor_sync(0xffffffffu, s1, 2);
    float w0 = wmix / s0, w1 = wmix / s1;
    pack_p(acc, pah, pal);
    attn_pv(pah, pal, sm + SLATH, sm + SLATL, 36, 0, acc);
#pragma unroll
    for (int nt = 0; nt < 8; nt++) {
      out[nt][0] = w0 * acc[nt][0]; out[nt][1] = w0 * acc[nt][1];
      out[nt][2] = w1 * acc[nt][2]; out[nt][3] = w1 * acc[nt][3];
    }
  }

  // swap token tile: K -> Q
  __syncthreads();
  load_tile(sm + TOKH, g_qh + tokbase, 128, 32, 64, 36, tid);
  load_tile(sm + TOKL, g_ql + tokbase, 128, 32, 64, 36, tid);
  __syncthreads();

  // ---- cross: softmax(Q . kc) @ vc ----
  attn_logits(sm + TOKH, sm + TOKL, wid * 16, sm + SKCH, sm + SKCL, 0, acc);
  {
    float s0 = 0.f, s1 = 0.f;
#pragma unroll
    for (int nt = 0; nt < 8; nt++) {
      acc[nt][0] = __expf(acc[nt][0]); acc[nt][1] = __expf(acc[nt][1]);
      acc[nt][2] = __expf(acc[nt][2]); acc[nt][3] = __expf(acc[nt][3]);
      s0 += acc[nt][0] + acc[nt][1];
      s1 += acc[nt][2] + acc[nt][3];
    }
    s0 += __shfl_xor_sync(0xffffffffu, s0, 1);
    s0 += __shfl_xor_sync(0xffffffffu, s0, 2);
    s1 += __shfl_xor_sync(0xffffffffu, s1, 1);
    s1 += __shfl_xor_sync(0xffffffffu, s1, 2);
    float w0 = (1.f - wmix) / s0, w1 = (1.f - wmix) / s1;
    pack_p(acc, pah, pal);
    attn_pv(pah, pal, sm + SVCH, sm + SVCL, 36, 0, acc);
#pragma unroll
    for (int nt = 0; nt < 8; nt++) {
      out[nt][0] += w0 * acc[nt][0]; out[nt][1] += w0 * acc[nt][1];
      out[nt][2] += w1 * acc[nt][2]; out[nt][3] += w1 * acc[nt][3];
    }
  }

  // write mix hi/lo
  int tok0 = c * 128 + wid * 16 + g;
#pragma unroll
  for (int nt = 0; nt < 8; nt++) {
    int col = h * 64 + nt * 8 + tg * 2;
    size_t a0 = ((size_t)(b * kN + tok0)) * 512 + col;
    uint32_t hi, lo;
    split2(out[nt][0], out[nt][1], hi, lo);
    *(uint32_t*)(g_mixh + a0) = hi;
    *(uint32_t*)(g_mixl + a0) = lo;
    split2(out[nt][2], out[nt][3], hi, lo);
    *(uint32_t*)(g_mixh + a0 + 8 * 512) = hi;
    *(uint32_t*)(g_mixl + a0 + 8 * 512) = lo;
  }
}

// ---------------- launch ----------------
extern "C" void kernel_launch(void* const* d_in, const int* in_sizes, int n_in,
                              void* d_out, int out_size) {
  const float* x    = (const float*)d_in[0];
  const float* ctx  = (const float*)d_in[1];
  const float* qg   = (const float*)d_in[2];
  const float* Wx   = (const float*)d_in[3];
  const float* bx   = (const float*)d_in[4];
  const float* Wk   = (const float*)d_in[5];
  const float* bk   = (const float*)d_in[6];
  const float* Wv   = (const float*)d_in[7];
  const float* bv   = (const float*)d_in[8];
  const float* Wcq  = (const float*)d_in[9];
  const float* bcq  = (const float*)d_in[10];
  const float* Wck  = (const float*)d_in[11];
  const float* bck  = (const float*)d_in[12];
  const float* Wcv  = (const float*)d_in[13];
  const float* bcv  = (const float*)d_in[14];
  const float* smx  = (const float*)d_in[15];
  const float* Wo   = (const float*)d_in[16];
  const float* bo   = (const float*)d_in[17];
  float* out = (float*)d_out;

  void *ahi_p, *alo_p, *whi_p, *wlo_p, *xh_p, *xl_p, *mh_p, *ml_p;
  cudaGetSymbolAddress(&ahi_p, g_ahi);
  cudaGetSymbolAddress(&alo_p, g_alo);
  cudaGetSymbolAddress(&whi_p, g_whi);
  cudaGetSymbolAddress(&wlo_p, g_wlo);
  cudaGetSymbolAddress(&xh_p, g_xh);
  cudaGetSymbolAddress(&xl_p, g_xl);
  cudaGetSymbolAddress(&mh_p, g_mixh);
  cudaGetSymbolAddress(&ml_p, g_mixl);

  cudaFuncSetAttribute(kvqenc, cudaFuncAttributeMaxDynamicSharedMemorySize,
                       KVQENC_SMEM);
  cudaFuncSetAttribute(dec_fused, cudaFuncAttributeMaxDynamicSharedMemorySize,
                       DEC_SMEM);

  const int nA4 = kROWS * kDIM / 4;   // 4194304 -> 16384 blocks
  const int nW4 = kDIM * kDIM / 4;    // 65536   -> 256 blocks

  // 1: split x + Wx in one launch
  conv2<<<nA4 / 256 + nW4 / 256, 256>>>(
      (const float4*)x, (uint2*)ahi_p, (uint2*)alo_p, nA4 / 256,
      (const float4*)Wx, (uint2*)whi_p, (uint2*)wlo_p);
  // 2: ctx proj + wkvq split + qg split
  prep_small<<<96, 256>>>(ctx, Wck, bck, Wcv, bcv, Wk, Wv, Wcq,
                          (const float4*)qg);
  // 3: proj1 -> xmid hi/lo
  mma512<1><<<dim3(4, kROWS / 128), 256>>>(
      (const uint4*)ahi_p, (const uint4*)alo_p, (const uint4*)whi_p,
      (const uint4*)wlo_p, bx, nullptr, (ushort*)xh_p, (ushort*)xl_p);
  // 4 (profiled slot): fused kvq + encode
  kvqenc<<<dim3(128, kBH), 256, KVQENC_SMEM>>>(bk, bv, bcq);
  // 5: reduce -> latent
  enc_reduce2<<<dim3(8, kBH), 256>>>();
  // 6: fused decode
  dec_fused<<<dim3(128, kBH), 256, DEC_SMEM>>>(smx);
  // 7: split Wo
  conv_split<<<nW4 / 256, 256>>>((const float4*)Wo, (uint2*)whi_p,
                                 (uint2*)wlo_p, nW4);
  // 8: proj2 -> out (f32)
  mma512<0><<<dim3(4, kROWS / 128), 256>>>(
      (const uint4*)mh_p, (const uint4*)ml_p, (const uint4*)whi_p,
      (const uint4*)wlo_p, bo, out, nullptr, nullptr);
}